// round 13
// baseline (speedup 1.0000x reference)
#include <cuda_runtime.h>
#include <cuda_bf16.h>
#include <stdint.h>

#define NB   8
#define NTOK 2048
#define DH   128
#define BQ   128          // attention q-rows per block (8 warps x m16)
#define BK   64
#define NKT  (NTOK / BK)   // 32
#define KPS  68            // K smem row stride (uint32)
#define VPS  36            // V^T smem row stride (uint32)
#define XSTR 68            // proj smem stride (uint32)

// ---- packed bf16 hi/lo scratch (pairs in uint32) ----
__device__ uint32_t g_qh[NB * NTOK * 64];
__device__ uint32_t g_ql[NB * NTOK * 64];
__device__ uint32_t g_kh[NB * NTOK * 64];
__device__ uint32_t g_kl[NB * NTOK * 64];
__device__ uint32_t g_vh[NB * DH * (NTOK / 2)];   // V transposed: [b][d][tokenpair]
__device__ uint32_t g_vl[NB * DH * (NTOK / 2)];
__device__ uint32_t g_wh[4 * 128 * 64];           // packed W: [proj][n][kpair]
__device__ uint32_t g_wl[4 * 128 * 64];

// attention smem (u32 offsets): K(2buf) | KL | V(2buf) | VL | uk2 | bks | WoH | WoL
#define KV_U32   (4 * 64 * KPS + 4 * 128 * VPS)   // 35840
#define WO_U32   (KV_U32 + 256 + 128)             // 36224
#define ATTN_U32 (WO_U32 + 2 * 8704)              // 53632
#define ATTN_SMEM (ATTN_U32 * 4)                  // 214528 B (1 block/SM)

#define QKV_SMEM  (2 * 8704 * 4)                  // single W buffer (hi+lo)

// m16n8k16 bf16 mma, D += A*B
#define MMA_BF16(d, a, b0, b1)                                                 \
  asm volatile(                                                                \
      "mma.sync.aligned.m16n8k16.row.col.f32.bf16.bf16.f32 "                   \
      "{%0,%1,%2,%3}, {%4,%5,%6,%7}, {%8,%9}, {%0,%1,%2,%3};"                  \
      : "+f"(d[0]), "+f"(d[1]), "+f"(d[2]), "+f"(d[3])                         \
      : "r"(a[0]), "r"(a[1]), "r"(a[2]), "r"(a[3]), "r"(b0), "r"(b1))

#define MMA6_INTERLEAVED(dA, dB, ah, al, h0, h1, h2, h3, l0, l1, l2, l3)       \
  do {                                                                         \
    MMA_BF16(dA, ah, h0, h1);                                                  \
    MMA_BF16(dB, ah, h2, h3);                                                  \
    MMA_BF16(dA, al, h0, h1);                                                  \
    MMA_BF16(dB, al, h2, h3);                                                  \
    MMA_BF16(dA, ah, l0, l1);                                                  \
    MMA_BF16(dB, ah, l2, l3);                                                  \
  } while (0)

__device__ __forceinline__ void ldsm4(uint32_t& r0, uint32_t& r1, uint32_t& r2,
                                      uint32_t& r3, uint32_t saddr) {
  asm volatile(
      "ldmatrix.sync.aligned.m8n8.x4.shared.b16 {%0,%1,%2,%3}, [%4];"
      : "=r"(r0), "=r"(r1), "=r"(r2), "=r"(r3)
      : "r"(saddr));
}

__device__ __forceinline__ uint32_t bfpack(float e, float o) {
  uint32_t r;
  asm("cvt.rn.bf16x2.f32 %0, %1, %2;" : "=r"(r) : "f"(o), "f"(e));
  return r;
}
__device__ __forceinline__ float bflo(uint32_t p) { return __uint_as_float(p << 16); }
__device__ __forceinline__ float bfhi(uint32_t p) { return __uint_as_float(p & 0xffff0000u); }
__device__ __forceinline__ uint32_t bfres(uint32_t h, float e, float o) {
  return bfpack(e - bflo(h), o - bfhi(h));
}

__device__ __forceinline__ void cp16(void* smem_dst, const void* gmem_src) {
  unsigned s = (unsigned)__cvta_generic_to_shared(smem_dst);
  asm volatile("cp.async.cg.shared.global [%0], [%1], 16;" ::"r"(s), "l"(gmem_src));
}
#define CP_COMMIT() asm volatile("cp.async.commit_group;")
#define CP_WAIT(n)  asm volatile("cp.async.wait_group %0;" ::"n"(n))

// ---------------------------------------------------------------------------
// Weight pre-pack: W[128k][128n] fp32 -> packed hi/lo [n][kpair] u32.
// Grid (16 kslices x 4 projs) = 64 blocks: 8 k-rows (4 kpairs) per block.
// ---------------------------------------------------------------------------
__global__ __launch_bounds__(256) void wpack_kernel(
    const float* __restrict__ Wq, const float* __restrict__ Wk,
    const float* __restrict__ Wv, const float* __restrict__ Wo,
    uint32_t* __restrict__ WH, uint32_t* __restrict__ WL) {
  __shared__ float Ws[8 * 132];
  const int ks = blockIdx.x, pj = blockIdx.y;
  const float* W = (pj == 0) ? Wq : (pj == 1) ? Wk : (pj == 2) ? Wv : Wo;
  const int tid = threadIdx.x;
#pragma unroll
  for (int it = 0; it < 4; it++) {
    int i = tid + it * 256;   // 0..1023
    int kr = i >> 7, n = i & 127;
    Ws[kr * 132 + n] = W[(ks * 8 + kr) * 128 + n];
  }
  __syncthreads();
#pragma unroll
  for (int it = 0; it < 2; it++) {
    int i = tid + it * 256;   // 0..511
    int n = i >> 2, kp4 = i & 3;
    float w0 = Ws[(2 * kp4) * 132 + n];
    float w1 = Ws[(2 * kp4 + 1) * 132 + n];
    uint32_t h = bfpack(w0, w1);
    int kp = ks * 4 + kp4;
    WH[pj * 8192 + n * 64 + kp] = h;
    WL[pj * 8192 + n * 64 + kp] = bfres(h, w0, w1);
  }
}

// ---------------------------------------------------------------------------
// Fused QKV projections, oproj-style: 64-token tiles, W-only smem (single
// buffer, 2 blocks/SM), X direct-LDG fragments, 3 phases with W(ph+1)
// prefetch overlapping the phase-ph epilogue. 8 warps: 4 row-groups x 2
// n-halves.
// ---------------------------------------------------------------------------
__global__ __launch_bounds__(256, 2) void qkv_kernel(
    const float* __restrict__ X, const uint32_t* __restrict__ WHg,
    const uint32_t* __restrict__ WLg,
    uint32_t* __restrict__ Qh, uint32_t* __restrict__ Ql,
    uint32_t* __restrict__ Kh, uint32_t* __restrict__ Kl,
    uint32_t* __restrict__ Vh, uint32_t* __restrict__ Vl) {
  extern __shared__ uint32_t usm[];   // Wh [128][XSTR] @0, Wl @8704 (u32)

  const int m0  = blockIdx.x * 64;
  const int tid = threadIdx.x;
  const int w = tid >> 5, lane = tid & 31;
  const int g = lane >> 2, t = lane & 3;
  const int wr = w & 3;              // row-group within 64-token tile
  const int jb = (w >> 2) * 4;       // n-pair base: 0 or 4
  const int r0 = wr * 16 + g, r1 = r0 + 8;
  const int lm = lane >> 3, lr = lane & 7;
  const uint32_t smb = (uint32_t)__cvta_generic_to_shared(usm);
  const uint32_t whb = smb;
  const uint32_t wlb = smb + 8704 * 4;
  const uint32_t wcc = ((8 * (lm >> 1) + lr) * XSTR + 4 * (lm & 1)) * 4;

  // prefetch W(0)
#pragma unroll
  for (int it = 0; it < 8; it++) {
    int i = tid + it * 256;
    int r = i >> 4, c = i & 15;
    cp16(usm + r * XSTR + c * 4, WHg + r * 64 + c * 4);
    cp16(usm + 8704 + r * XSTR + c * 4, WLg + r * 64 + c * 4);
  }
  CP_COMMIT();

  // X direct LDG -> split -> fragments (overlaps W(0) load)
  uint32_t xah[8][4], xal[8][4];
  const float* Xr0 = X + (size_t)(m0 + r0) * DH;
  const float* Xr1 = X + (size_t)(m0 + r1) * DH;
#pragma unroll
  for (int s = 0; s < 8; s++) {
    float2 a = *reinterpret_cast<const float2*>(Xr0 + 16 * s + 2 * t);
    float2 bv = *reinterpret_cast<const float2*>(Xr1 + 16 * s + 2 * t);
    float2 c = *reinterpret_cast<const float2*>(Xr0 + 16 * s + 2 * t + 8);
    float2 d = *reinterpret_cast<const float2*>(Xr1 + 16 * s + 2 * t + 8);
    xah[s][0] = bfpack(a.x, a.y);  xal[s][0] = bfres(xah[s][0], a.x, a.y);
    xah[s][1] = bfpack(bv.x, bv.y); xal[s][1] = bfres(xah[s][1], bv.x, bv.y);
    xah[s][2] = bfpack(c.x, c.y);  xal[s][2] = bfres(xah[s][2], c.x, c.y);
    xah[s][3] = bfpack(d.x, d.y);  xal[s][3] = bfres(xah[s][3], d.x, d.y);
  }
  CP_WAIT(0);
  __syncthreads();

#pragma unroll 1
  for (int ph = 0; ph < 3; ph++) {
    float acc[8][4];
#pragma unroll
    for (int j = 0; j < 8; j++)
#pragma unroll
      for (int q = 0; q < 4; q++) acc[j][q] = 0.f;

#pragma unroll
    for (int s = 0; s < 8; s++) {
#pragma unroll
      for (int jp2 = 0; jp2 < 4; jp2++) {
        int jp = jb + jp2;
        uint32_t h0, h1, h2, h3, l0, l1, l2, l3;
        ldsm4(h0, h1, h2, h3, whb + jp * (16 * XSTR * 4) + s * 32 + wcc);
        ldsm4(l0, l1, l2, l3, wlb + jp * (16 * XSTR * 4) + s * 32 + wcc);
        MMA6_INTERLEAVED(acc[2 * jp2], acc[2 * jp2 + 1], xah[s], xal[s],
                         h0, h1, h2, h3, l0, l1, l2, l3);
      }
    }
    __syncthreads();  // all warps done reading W(ph)

    if (ph < 2) {  // prefetch W(ph+1) into the (single) buffer; overlaps stores
#pragma unroll
      for (int it = 0; it < 8; it++) {
        int i = tid + it * 256;
        int r = i >> 4, c = i & 15;
        cp16(usm + r * XSTR + c * 4, WHg + (ph + 1) * 8192 + r * 64 + c * 4);
        cp16(usm + 8704 + r * XSTR + c * 4,
             WLg + (ph + 1) * 8192 + r * 64 + c * 4);
      }
      CP_COMMIT();
    }

    if (ph < 2) {
      // Q/K epilogue: pack pairs over d -> [tok][64 u32] hi/lo
      uint32_t* Oh = (ph == 0) ? Qh : Kh;
      uint32_t* Ol = (ph == 0) ? Ql : Kl;
      const float sc = (ph == 0) ? 0.088388347648318447f : 1.0f;
#pragma unroll
      for (int j = 0; j < 8; j++) {
        int p = (2 * jb + j) * 4 + t;   // pair index = col/2
        float a0 = acc[j][0] * sc, a1 = acc[j][1] * sc;
        float a2 = acc[j][2] * sc, a3 = acc[j][3] * sc;
        uint32_t h0 = bfpack(a0, a1), h1 = bfpack(a2, a3);
        Oh[(size_t)(m0 + r0) * 64 + p] = h0;
        Ol[(size_t)(m0 + r0) * 64 + p] = bfres(h0, a0, a1);
        Oh[(size_t)(m0 + r1) * 64 + p] = h1;
        Ol[(size_t)(m0 + r1) * 64 + p] = bfres(h1, a2, a3);
      }
      CP_WAIT(0);
      __syncthreads();
    } else {
      // V epilogue: transpose via W buffer (now dead), pack pairs over tokens
      uint16_t* Th = (uint16_t*)usm;            // [128 d][66 tok]
      uint16_t* Tl = Th + 128 * 66;
#pragma unroll
      for (int j = 0; j < 8; j++) {
        int c0 = (2 * jb + j) * 8 + 2 * t, c1 = c0 + 1;
#pragma unroll
        for (int q = 0; q < 4; q++) {
          int c = (q & 1) ? c1 : c0;
          int r = (q & 2) ? r1 : r0;
          float x = acc[j][q];
          __nv_bfloat16 h = __float2bfloat16(x);
          Th[c * 66 + r] = __bfloat16_as_ushort(h);
          Tl[c * 66 + r] =
              __bfloat16_as_ushort(__float2bfloat16(x - __bfloat162float(h)));
        }
      }
      __syncthreads();
      const int bb = m0 >> 11;
      const int loc2 = (m0 & 2047) >> 1;
      const uint32_t* Th32 = (const uint32_t*)Th;
      const uint32_t* Tl32 = (const uint32_t*)Tl;
#pragma unroll
      for (int it = 0; it < 16; it++) {
        int i = tid + it * 256;  // 0..4095
        int d = i >> 5, m = i & 31;
        size_t go = (size_t)(bb * DH + d) * (NTOK / 2) + loc2 + m;
        Vh[go] = Th32[d * 33 + m];
        Vl[go] = Tl32[d * 33 + m];
      }
    }
  }
}

// ---------------------------------------------------------------------------
// Fused flash attention + output projection (unchanged 184.9us winner).
// ---------------------------------------------------------------------------
__global__ __launch_bounds__(256, 1) void attn_kernel(
    const uint32_t* __restrict__ QpH, const uint32_t* __restrict__ QpL,
    const uint32_t* __restrict__ KpH, const uint32_t* __restrict__ KpL,
    const uint32_t* __restrict__ VpH, const uint32_t* __restrict__ VpL,
    const uint32_t* __restrict__ WHg, const uint32_t* __restrict__ WLg,
    const float* __restrict__ allele, const float* __restrict__ mask,
    float* __restrict__ Out) {
  extern __shared__ uint32_t usm[];
  uint32_t* KH = usm;                      // [2][64*KPS]
  uint32_t* KL = KH + 2 * 64 * KPS;
  uint32_t* VH = KL + 2 * 64 * KPS;        // [2][128*VPS]
  uint32_t* VL = VH + 2 * 128 * VPS;
  float2*   uk2 = (float2*)(VL + 2 * 128 * VPS);  // [2][64] (u, 1/u)
  float*    bks = (float*)(uk2 + 128);            // [2][64] bias - 16

  const int b   = blockIdx.y;
  const int q0  = blockIdx.x * BQ;
  const int tid = threadIdx.x;
  const int w = tid >> 5, lane = tid & 31;
  const int g = lane >> 2, t = lane & 3;
  const int lm = lane >> 3, lr = lane & 7;
  const uint32_t smb = (uint32_t)__cvta_generic_to_shared(usm);
  const uint32_t kcc = ((8 * (lm >> 1) + lr) * KPS + 4 * (lm & 1)) * 4;
  const uint32_t vcc = ((8 * (lm >> 1) + lr) * VPS + 4 * (lm & 1)) * 4;
  const uint32_t VH_OFF = (4 * 64 * KPS) * 4;
  const uint32_t VL_OFF = VH_OFF + (2 * 128 * VPS) * 4;

  // ---- Q fragments direct from global (pre-scaled, packed hi/lo)
  const uint32_t* qhg = QpH + (size_t)(b * NTOK + q0 + w * 16) * 64;
  const uint32_t* qlg = QpL + (size_t)(b * NTOK + q0 + w * 16) * 64;
  uint32_t qah[8][4], qal[8][4];
#pragma unroll
  for (int s = 0; s < 8; s++) {
    qah[s][0] = qhg[g * 64 + 8 * s + t];
    qah[s][1] = qhg[(g + 8) * 64 + 8 * s + t];
    qah[s][2] = qhg[g * 64 + 8 * s + t + 4];
    qah[s][3] = qhg[(g + 8) * 64 + 8 * s + t + 4];
    qal[s][0] = qlg[g * 64 + 8 * s + t];
    qal[s][1] = qlg[(g + 8) * 64 + 8 * s + t];
    qal[s][2] = qlg[g * 64 + 8 * s + t + 4];
    qal[s][3] = qlg[(g + 8) * 64 + 8 * s + t + 4];
  }
  float aq0 = allele[b * NTOK + q0 + w * 16 + g];
  float aq1 = allele[b * NTOK + q0 + w * 16 + g + 8];
  float uq0 = __expf(0.1f * aq0), iq0 = 1.0f / uq0;
  float uq1 = __expf(0.1f * aq1), iq1 = 1.0f / uq1;

  // ---- prefetch tile 0 + packed Wo (one cp group)
  {
    const uint32_t* kh = KpH + (size_t)(b * NTOK) * 64;
    const uint32_t* kl = KpL + (size_t)(b * NTOK) * 64;
#pragma unroll
    for (int it = 0; it < 4; it++) {
      int i = tid + it * 256;
      int r = i >> 4, c = i & 15;
      cp16(&KH[r * KPS + c * 4], kh + r * 64 + c * 4);
      cp16(&KL[r * KPS + c * 4], kl + r * 64 + c * 4);
    }
    const uint32_t* vh = VpH + (size_t)b * DH * (NTOK / 2);
    const uint32_t* vl = VpL + (size_t)b * DH * (NTOK / 2);
#pragma unroll
    for (int it = 0; it < 4; it++) {
      int i = tid + it * 256;
      int r = i >> 3, c = i & 7;
      cp16(&VH[r * VPS + c * 4], vh + (size_t)r * (NTOK / 2) + c * 4);
      cp16(&VL[r * VPS + c * 4], vl + (size_t)r * (NTOK / 2) + c * 4);
    }
    // Wo hi/lo -> smem (rows n, stride XSTR)
#pragma unroll
    for (int it = 0; it < 8; it++) {
      int i = tid + it * 256;
      int r = i >> 4, c = i & 15;
      cp16(usm + WO_U32 + r * XSTR + c * 4, WHg + 3 * 8192 + r * 64 + c * 4);
      cp16(usm + WO_U32 + 8704 + r * XSTR + c * 4,
           WLg + 3 * 8192 + r * 64 + c * 4);
    }
    CP_COMMIT();
    if (tid < BK) {
      float a = allele[b * NTOK + tid];
      float u = __expf(0.1f * a);
      uk2[tid] = make_float2(u, 1.0f / u);
      bks[tid] = (1.0f - mask[b * NTOK + tid]) * -1e9f - 16.0f;
    }
  }

  float o[16][4];
#pragma unroll
  for (int j = 0; j < 16; j++)
#pragma unroll
    for (int q = 0; q < 4; q++) o[j][q] = 0.f;
  float sum0 = 0.f, sum1 = 0.f;   // running exp-sums (fixed shift)

#pragma unroll 1
  for (int kt = 0; kt < NKT; kt++) {
    const int buf = kt & 1;
    CP_WAIT(0);
    __syncthreads();

    if (kt + 1 < NKT) {
      const uint32_t* kh = KpH + (size_t)(b * NTOK + (kt + 1) * BK) * 64;
      const uint32_t* kl = KpL + (size_t)(b * NTOK + (kt + 1) * BK) * 64;
      uint32_t* dkh = KH + (buf ^ 1) * 64 * KPS;
      uint32_t* dkl = KL + (buf ^ 1) * 64 * KPS;
#pragma unroll
      for (int it = 0; it < 4; it++) {
        int i = tid + it * 256;
        int r = i >> 4, c = i & 15;
        cp16(dkh + r * KPS + c * 4, kh + r * 64 + c * 4);
        cp16(dkl + r * KPS + c * 4, kl + r * 64 + c * 4);
      }
      const uint32_t* vh = VpH + (size_t)b * DH * (NTOK / 2) + (kt + 1) * 32;
      const uint32_t* vl = VpL + (size_t)b * DH * (NTOK / 2) + (kt + 1) * 32;
      uint32_t* dvh = VH + (buf ^ 1) * 128 * VPS;
      uint32_t* dvl = VL + (buf ^ 1) * 128 * VPS;
#pragma unroll
      for (int it = 0; it < 4; it++) {
        int i = tid + it * 256;
        int r = i >> 3, c = i & 7;
        cp16(dvh + r * VPS + c * 4, vh + (size_t)r * (NTOK / 2) + c * 4);
        cp16(dvl + r * VPS + c * 4, vl + (size_t)r * (NTOK / 2) + c * 4);
      }
      CP_COMMIT();
      if (tid < BK) {
        float a = allele[b * NTOK + (kt + 1) * BK + tid];
        float u = __expf(0.1f * a);
        uk2[(buf ^ 1) * 64 + tid] = make_float2(u, 1.0f / u);
        bks[(buf ^ 1) * 64 + tid] =
            (1.0f - mask[b * NTOK + (kt + 1) * BK + tid]) * -1e9f - 16.0f;
      }
    }

    // ---- S = Q K^T (m16 x n64 x k128, 3-mma split, ldmatrix B)
    float sacc[8][4];
#pragma unroll
    for (int j = 0; j < 8; j++)
#pragma unroll
      for (int q = 0; q < 4; q++) sacc[j][q] = 0.f;

    const uint32_t khb = smb + (buf * 64 * KPS) * 4;
    const uint32_t klb = smb + ((2 + buf) * 64 * KPS) * 4;
#pragma unroll
    for (int s = 0; s < 8; s++) {
#pragma unroll
      for (int jp = 0; jp < 4; jp++) {
        uint32_t h0, h1, h2, h3, l0_, l1_, l2_, l3_;
        ldsm4(h0, h1, h2, h3, khb + jp * (16 * KPS * 4) + s * 32 + kcc);
        ldsm4(l0_, l1_, l2_, l3_, klb + jp * (16 * KPS * 4) + s * 32 + kcc);
        MMA6_INTERLEAVED(sacc[2 * jp], sacc[2 * jp + 1], qah[s], qal[s],
                         h0, h1, h2, h3, l0_, l1_, l2_, l3_);
      }
    }

    // ---- fixed-shift softmax: P = exp(S*decay + bias') directly
    const float2* ukb = &uk2[buf * 64];
    const float*  bb  = &bks[buf * 64];
    uint32_t pah[4][4], pal[4][4];
#pragma unroll
    for (int j = 0; j < 8; j++) {
      int c = 8 * j + 2 * t;
      float4 uu = *reinterpret_cast<const float4*>(&ukb[c]);
      float2 bias = *reinterpret_cast<const float2*>(&bb[c]);
      float d00 = fminf(uq0 * uu.y, iq0 * uu.x);
      float d01 = fminf(uq0 * uu.w, iq0 * uu.z);
      float d10 = fminf(uq1 * uu.y, iq1 * uu.x);
      float d11 = fminf(uq1 * uu.w, iq1 * uu.z);
      float p00 = __expf(fmaf(sacc[j][0], d00, bias.x));
      float p01 = __expf(fmaf(sacc[j][1], d01, bias.y));
      float p10 = __expf(fmaf(sacc[j][2], d10, bias.x));
      float p11 = __expf(fmaf(sacc[j][3], d11, bias.y));
      sum0 += p00 + p01;
      sum1 += p10 + p11;
      int s2 = j >> 1, sl = (j & 1) * 2;
      pah[s2][sl]     = bfpack(p00, p01);
      pal[s2][sl]     = bfres(pah[s2][sl], p00, p01);
      pah[s2][sl + 1] = bfpack(p10, p11);
      pal[s2][sl + 1] = bfres(pah[s2][sl + 1], p10, p11);
    }

    // ---- O += P V (m16 x n128 x k64)
    const uint32_t vhb = smb + VH_OFF + (buf * 128 * VPS) * 4;
    const uint32_t vlb = smb + VL_OFF + (buf * 128 * VPS) * 4;
#pragma unroll
    for (int s2 = 0; s2 < 4; s2++) {
#pragma unroll
      for (int jp2 = 0; jp2 < 8; jp2++) {
        uint32_t h0, h1, h2, h3, l0_, l1_, l2_, l3_;
        ldsm4(h0, h1, h2, h3, vhb + jp2 * (16 * VPS * 4) + s2 * 32 + vcc);
        ldsm4(l0_, l1_, l2_, l3_, vlb + jp2 * (16 * VPS * 4) + s2 * 32 + vcc);
        MMA6_INTERLEAVED(o[2 * jp2], o[2 * jp2 + 1], pah[s2], pal[s2],
                         h0, h1, h2, h3, l0_, l1_, l2_, l3_);
      }
    }
  }

  // ---- epilogue: normalize, then out = ctx @ Wo fused in-register.
  sum0 += __shfl_xor_sync(0xffffffffu, sum0, 1);
  sum0 += __shfl_xor_sync(0xffffffffu, sum0, 2);
  sum1 += __shfl_xor_sync(0xffffffffu, sum1, 1);
  sum1 += __shfl_xor_sync(0xffffffffu, sum1, 2);
  float inv0 = 1.0f / sum0, inv1 = 1.0f / sum1;

  const uint32_t wohb = smb + WO_U32 * 4;
  const uint32_t wolb = wohb + 8704 * 4;
  const uint32_t wcc = ((8 * (lm >> 1) + lr) * XSTR + 4 * (lm & 1)) * 4;

  float out[16][4];
#pragma unroll
  for (int j = 0; j < 16; j++)
#pragma unroll
    for (int q = 0; q < 4; q++) out[j][q] = 0.f;

#pragma unroll
  for (int s = 0; s < 8; s++) {
    float f0 = o[2 * s][0] * inv0, f1 = o[2 * s][1] * inv0;
    float f2 = o[2 * s][2] * inv1, f3 = o[2 * s][3] * inv1;
    float e0 = o[2 * s + 1][0] * inv0, e1 = o[2 * s + 1][1] * inv0;
    float e2 = o[2 * s + 1][2] * inv1, e3 = o[2 * s + 1][3] * inv1;
    uint32_t cah[4], cal[4];
    cah[0] = bfpack(f0, f1); cal[0] = bfres(cah[0], f0, f1);
    cah[1] = bfpack(f2, f3); cal[1] = bfres(cah[1], f2, f3);
    cah[2] = bfpack(e0, e1); cal[2] = bfres(cah[2], e0, e1);
    cah[3] = bfpack(e2, e3); cal[3] = bfres(cah[3], e2, e3);
#pragma unroll
    for (int jp = 0; jp < 8; jp++) {
      uint32_t h0, h1, h2, h3, l0_, l1_, l2_, l3_;
      ldsm4(h0, h1, h2, h3, wohb + jp * (16 * XSTR * 4) + s * 32 + wcc);
      ldsm4(l0_, l1_, l2_, l3_, wolb + jp * (16 * XSTR * 4) + s * 32 + wcc);
      MMA6_INTERLEAVED(out[2 * jp], out[2 * jp + 1], cah, cal,
                       h0, h1, h2, h3, l0_, l1_, l2_, l3_);
    }
  }

  float* Og = Out + (size_t)(b * NTOK + q0) * DH;
#pragma unroll
  for (int j2 = 0; j2 < 16; j2++) {
    *reinterpret_cast<float2*>(&Og[(w * 16 + g) * DH + 8 * j2 + 2 * t]) =
        make_float2(out[j2][0], out[j2][1]);
    *reinterpret_cast<float2*>(&Og[(w * 16 + g + 8) * DH + 8 * j2 + 2 * t]) =
        make_float2(out[j2][2], out[j2][3]);
  }
}

// ---------------------------------------------------------------------------
extern "C" void kernel_launch(void* const* d_in, const int* in_sizes, int n_in,
                              void* d_out, int out_size) {
  const float* X  = (const float*)d_in[0];
  const float* al = (const float*)d_in[1];
  const float* mk = (const float*)d_in[2];
  const float* Wq = (const float*)d_in[3];
  const float* Wk = (const float*)d_in[4];
  const float* Wv = (const float*)d_in[5];
  const float* Wo = (const float*)d_in[6];
  float* out = (float*)d_out;

  uint32_t *qh, *ql, *kh, *kl, *vh, *vl, *wh, *wl;
  cudaGetSymbolAddress((void**)&qh, g_qh);
  cudaGetSymbolAddress((void**)&ql, g_ql);
  cudaGetSymbolAddress((void**)&kh, g_kh);
  cudaGetSymbolAddress((void**)&kl, g_kl);
  cudaGetSymbolAddress((void**)&vh, g_vh);
  cudaGetSymbolAddress((void**)&vl, g_vl);
  cudaGetSymbolAddress((void**)&wh, g_wh);
  cudaGetSymbolAddress((void**)&wl, g_wl);

  cudaFuncSetAttribute(qkv_kernel,
                       cudaFuncAttributeMaxDynamicSharedMemorySize, QKV_SMEM);
  cudaFuncSetAttribute(attn_kernel,
                       cudaFuncAttributeMaxDynamicSharedMemorySize, ATTN_SMEM);

  wpack_kernel<<<dim3(16, 4), 256>>>(Wq, Wk, Wv, Wo, wh, wl);
  qkv_kernel<<<NB * NTOK / 64, 256, QKV_SMEM>>>(X, wh, wl, qh, ql, kh, kl, vh, vl);
  attn_kernel<<<dim3(NTOK / BQ, NB), 256, ATTN_SMEM>>>(qh, ql, kh, kl, vh, vl,
                                                       wh, wl, al, mk, out);
}

// round 14
// speedup vs baseline: 1.0102x; 1.0102x over previous
#include <cuda_runtime.h>
#include <cuda_bf16.h>
#include <stdint.h>

#define NB   8
#define NTOK 2048
#define DH   128
#define BQ   128          // attention q-rows per block (8 warps x m16)
#define BK   64
#define NKT  (NTOK / BK)   // 32
#define KPS  68            // K smem row stride (uint32)
#define VPS  36            // V^T smem row stride (uint32)
#define XSTR 68            // proj smem stride (uint32)

// ---- packed bf16 hi/lo scratch (pairs in uint32) ----
__device__ uint32_t g_qh[NB * NTOK * 64];
__device__ uint32_t g_ql[NB * NTOK * 64];
__device__ uint32_t g_kh[NB * NTOK * 64];
__device__ uint32_t g_kl[NB * NTOK * 64];
__device__ uint32_t g_vh[NB * DH * (NTOK / 2)];   // V transposed: [b][d][tokenpair]
__device__ uint32_t g_vl[NB * DH * (NTOK / 2)];
__device__ uint32_t g_wh[4 * 128 * 64];           // packed W: [proj][n][kpair]
__device__ uint32_t g_wl[4 * 128 * 64];

// attention smem (u32 offsets): K(2buf) | KL | V(2buf) | VL | uk2 | bks | WoH | WoL
#define KV_U32   (4 * 64 * KPS + 4 * 128 * VPS)   // 35840
#define WO_U32   (KV_U32 + 256 + 128)             // 36224
#define ATTN_U32 (WO_U32 + 2 * 8704)              // 53632
#define ATTN_SMEM (ATTN_U32 * 4)                  // 214528 B (1 block/SM)

#define QKV_SMEM  ((2 * 128 * XSTR + 2 * 2 * 128 * XSTR) * 4)  // X + 2 W bufs

// m16n8k16 bf16 mma, D += A*B
#define MMA_BF16(d, a, b0, b1)                                                 \
  asm volatile(                                                                \
      "mma.sync.aligned.m16n8k16.row.col.f32.bf16.bf16.f32 "                   \
      "{%0,%1,%2,%3}, {%4,%5,%6,%7}, {%8,%9}, {%0,%1,%2,%3};"                  \
      : "+f"(d[0]), "+f"(d[1]), "+f"(d[2]), "+f"(d[3])                         \
      : "r"(a[0]), "r"(a[1]), "r"(a[2]), "r"(a[3]), "r"(b0), "r"(b1))

#define MMA6_INTERLEAVED(dA, dB, ah, al, h0, h1, h2, h3, l0, l1, l2, l3)       \
  do {                                                                         \
    MMA_BF16(dA, ah, h0, h1);                                                  \
    MMA_BF16(dB, ah, h2, h3);                                                  \
    MMA_BF16(dA, al, h0, h1);                                                  \
    MMA_BF16(dB, al, h2, h3);                                                  \
    MMA_BF16(dA, ah, l0, l1);                                                  \
    MMA_BF16(dB, ah, l2, l3);                                                  \
  } while (0)

__device__ __forceinline__ void ldsm4(uint32_t& r0, uint32_t& r1, uint32_t& r2,
                                      uint32_t& r3, uint32_t saddr) {
  asm volatile(
      "ldmatrix.sync.aligned.m8n8.x4.shared.b16 {%0,%1,%2,%3}, [%4];"
      : "=r"(r0), "=r"(r1), "=r"(r2), "=r"(r3)
      : "r"(saddr));
}

__device__ __forceinline__ uint32_t bfpack(float e, float o) {
  uint32_t r;
  asm("cvt.rn.bf16x2.f32 %0, %1, %2;" : "=r"(r) : "f"(o), "f"(e));
  return r;
}
__device__ __forceinline__ float bflo(uint32_t p) { return __uint_as_float(p << 16); }
__device__ __forceinline__ float bfhi(uint32_t p) { return __uint_as_float(p & 0xffff0000u); }
__device__ __forceinline__ uint32_t bfres(uint32_t h, float e, float o) {
  return bfpack(e - bflo(h), o - bfhi(h));
}

__device__ __forceinline__ void cp16(void* smem_dst, const void* gmem_src) {
  unsigned s = (unsigned)__cvta_generic_to_shared(smem_dst);
  asm volatile("cp.async.cg.shared.global [%0], [%1], 16;" ::"r"(s), "l"(gmem_src));
}
#define CP_COMMIT() asm volatile("cp.async.commit_group;")
#define CP_WAIT(n)  asm volatile("cp.async.wait_group %0;" ::"n"(n))

// ---------------------------------------------------------------------------
// Weight pre-pack: W[128k][128n] fp32 -> packed hi/lo [n][kpair] u32.
// Wq is pre-scaled by 1/sqrt(128) (folded out of the qkv Q epilogue).
// ---------------------------------------------------------------------------
__global__ __launch_bounds__(256) void wpack_kernel(
    const float* __restrict__ Wq, const float* __restrict__ Wk,
    const float* __restrict__ Wv, const float* __restrict__ Wo,
    uint32_t* __restrict__ WH, uint32_t* __restrict__ WL) {
  __shared__ float Ws[32 * 132];
  const int ks = blockIdx.x, pj = blockIdx.y;
  const float* W = (pj == 0) ? Wq : (pj == 1) ? Wk : (pj == 2) ? Wv : Wo;
  const float sc = (pj == 0) ? 0.088388347648318447f : 1.0f;
  const int tid = threadIdx.x;
#pragma unroll
  for (int it = 0; it < 16; it++) {
    int i = tid + it * 256;
    int kr = i >> 7, n = i & 127;
    Ws[kr * 132 + n] = W[(ks * 32 + kr) * 128 + n] * sc;
  }
  __syncthreads();
#pragma unroll
  for (int it = 0; it < 8; it++) {
    int i = tid + it * 256;
    int n = i >> 4, kp = i & 15;
    float w0 = Ws[(2 * kp) * 132 + n];
    float w1 = Ws[(2 * kp + 1) * 132 + n];
    uint32_t h = bfpack(w0, w1);
    WH[pj * 8192 + n * 64 + ks * 16 + kp] = h;
    WL[pj * 8192 + n * 64 + ks * 16 + kp] = bfres(h, w0, w1);
  }
}

// ---------------------------------------------------------------------------
// Fused QKV projections (R11/184.9us configuration): 128-token tiles, X
// staged in smem, packed W via double-buffered cp.async, 3 phases.
// ---------------------------------------------------------------------------
__global__ __launch_bounds__(256, 1) void qkv_kernel(
    const float* __restrict__ X, const uint32_t* __restrict__ WHg,
    const uint32_t* __restrict__ WLg,
    uint32_t* __restrict__ Qh, uint32_t* __restrict__ Ql,
    uint32_t* __restrict__ Kh, uint32_t* __restrict__ Kl,
    uint32_t* __restrict__ Vh, uint32_t* __restrict__ Vl) {
  extern __shared__ uint32_t usm[];
  uint32_t* Xh = usm;                  // [128][XSTR]
  uint32_t* Xl = Xh + 128 * XSTR;

  const int m0  = blockIdx.x * 128;
  const int tid = threadIdx.x;
  const int w = tid >> 5, lane = tid & 31;
  const int g = lane >> 2, t = lane & 3;
  const int r0 = w * 16 + g, r1 = r0 + 8;
  const int lm = lane >> 3, lr = lane & 7;
  const uint32_t smb = (uint32_t)__cvta_generic_to_shared(usm);
  const uint32_t wcc = ((8 * (lm >> 1) + lr) * XSTR + 4 * (lm & 1)) * 4;

  // prologue: prefetch W0
#pragma unroll
  for (int it = 0; it < 8; it++) {
    int i = tid + it * 256;
    int r = i >> 4, c = i & 15;
    cp16(usm + 17408 + r * XSTR + c * 4, WHg + r * 64 + c * 4);
    cp16(usm + 17408 + 8704 + r * XSTR + c * 4, WLg + r * 64 + c * 4);
  }
  CP_COMMIT();

  // stage X split+packed (overlaps W0 load)
#pragma unroll
  for (int it = 0; it < 16; it++) {
    int i = tid + it * 256;
    int r = i >> 5, c4 = i & 31;
    float4 xv = reinterpret_cast<const float4*>(X)[(size_t)(m0 + r) * 32 + c4];
    uint32_t h0 = bfpack(xv.x, xv.y), h1 = bfpack(xv.z, xv.w);
    Xh[r * XSTR + 2 * c4]     = h0;
    Xh[r * XSTR + 2 * c4 + 1] = h1;
    Xl[r * XSTR + 2 * c4]     = bfres(h0, xv.x, xv.y);
    Xl[r * XSTR + 2 * c4 + 1] = bfres(h1, xv.z, xv.w);
  }
  __syncthreads();

  uint32_t xah[8][4], xal[8][4];
#pragma unroll
  for (int s = 0; s < 8; s++) {
    xah[s][0] = Xh[r0 * XSTR + 8 * s + t];
    xah[s][1] = Xh[r1 * XSTR + 8 * s + t];
    xah[s][2] = Xh[r0 * XSTR + 8 * s + t + 4];
    xah[s][3] = Xh[r1 * XSTR + 8 * s + t + 4];
    xal[s][0] = Xl[r0 * XSTR + 8 * s + t];
    xal[s][1] = Xl[r1 * XSTR + 8 * s + t];
    xal[s][2] = Xl[r0 * XSTR + 8 * s + t + 4];
    xal[s][3] = Xl[r1 * XSTR + 8 * s + t + 4];
  }

#pragma unroll 1
  for (int ph = 0; ph < 3; ph++) {
    if (ph < 2) {
      const uint32_t buf1 = ((ph + 1) & 1);
      uint32_t* wb = usm + 17408 + buf1 * 17408;
#pragma unroll
      for (int it = 0; it < 8; it++) {
        int i = tid + it * 256;
        int r = i >> 4, c = i & 15;
        cp16(wb + r * XSTR + c * 4, WHg + (ph + 1) * 8192 + r * 64 + c * 4);
        cp16(wb + 8704 + r * XSTR + c * 4, WLg + (ph + 1) * 8192 + r * 64 + c * 4);
      }
      CP_COMMIT();
      CP_WAIT(1);
    } else {
      CP_WAIT(0);
    }
    __syncthreads();

    const uint32_t whb = smb + (17408 + (ph & 1) * 17408) * 4;
    const uint32_t wlb = whb + 8704 * 4;

    float acc[16][4];
#pragma unroll
    for (int j = 0; j < 16; j++)
#pragma unroll
      for (int q = 0; q < 4; q++) acc[j][q] = 0.f;

#pragma unroll
    for (int s = 0; s < 8; s++) {
#pragma unroll
      for (int jp = 0; jp < 8; jp++) {
        uint32_t h0, h1, h2, h3, l0, l1, l2, l3;
        ldsm4(h0, h1, h2, h3, whb + jp * (16 * XSTR * 4) + s * 32 + wcc);
        ldsm4(l0, l1, l2, l3, wlb + jp * (16 * XSTR * 4) + s * 32 + wcc);
        MMA6_INTERLEAVED(acc[2 * jp], acc[2 * jp + 1], xah[s], xal[s],
                         h0, h1, h2, h3, l0, l1, l2, l3);
      }
    }

    if (ph < 2) {
      // Q/K epilogue (identical both phases; Wq pre-scaled in wpack)
      uint32_t* Oh = (ph == 0) ? Qh : Kh;
      uint32_t* Ol = (ph == 0) ? Ql : Kl;
#pragma unroll
      for (int j = 0; j < 16; j++) {
        float a0 = acc[j][0], a1 = acc[j][1];
        float a2 = acc[j][2], a3 = acc[j][3];
        uint32_t h0 = bfpack(a0, a1), h1 = bfpack(a2, a3);
        Oh[(size_t)(m0 + r0) * 64 + 4 * j + t] = h0;
        Ol[(size_t)(m0 + r0) * 64 + 4 * j + t] = bfres(h0, a0, a1);
        Oh[(size_t)(m0 + r1) * 64 + 4 * j + t] = h1;
        Ol[(size_t)(m0 + r1) * 64 + 4 * j + t] = bfres(h1, a2, a3);
      }
    } else {
      // V: transpose via the free W buffer, pack pairs over tokens
      __syncthreads();
      uint16_t* Th = (uint16_t*)(usm + 17408 + 17408);  // [128 d][132 tok]
      uint16_t* Tl = Th + 128 * 132;
#pragma unroll
      for (int j = 0; j < 16; j++) {
        int c0 = 8 * j + 2 * t, c1 = c0 + 1;
#pragma unroll
        for (int q = 0; q < 4; q++) {
          int c = (q & 1) ? c1 : c0;
          int r = (q & 2) ? r1 : r0;
          float x = acc[j][q];
          __nv_bfloat16 h = __float2bfloat16(x);
          Th[c * 132 + r] = __bfloat16_as_ushort(h);
          Tl[c * 132 + r] =
              __bfloat16_as_ushort(__float2bfloat16(x - __bfloat162float(h)));
        }
      }
      __syncthreads();
      const int bb = m0 >> 11;
      const int loc2 = (m0 & 2047) >> 1;
      const uint32_t* Th32 = (const uint32_t*)Th;
      const uint32_t* Tl32 = (const uint32_t*)Tl;
#pragma unroll
      for (int it = 0; it < 32; it++) {
        int i = tid + it * 256;
        int d = i >> 6, m = i & 63;
        size_t go = (size_t)(bb * DH + d) * (NTOK / 2) + loc2 + m;
        Vh[go] = Th32[d * 66 + m];
        Vl[go] = Tl32[d * 66 + m];
      }
    }
  }
}

// ---------------------------------------------------------------------------
// Fused flash attention + output projection (unchanged 184.9us winner).
// ---------------------------------------------------------------------------
__global__ __launch_bounds__(256, 1) void attn_kernel(
    const uint32_t* __restrict__ QpH, const uint32_t* __restrict__ QpL,
    const uint32_t* __restrict__ KpH, const uint32_t* __restrict__ KpL,
    const uint32_t* __restrict__ VpH, const uint32_t* __restrict__ VpL,
    const uint32_t* __restrict__ WHg, const uint32_t* __restrict__ WLg,
    const float* __restrict__ allele, const float* __restrict__ mask,
    float* __restrict__ Out) {
  extern __shared__ uint32_t usm[];
  uint32_t* KH = usm;                      // [2][64*KPS]
  uint32_t* KL = KH + 2 * 64 * KPS;
  uint32_t* VH = KL + 2 * 64 * KPS;        // [2][128*VPS]
  uint32_t* VL = VH + 2 * 128 * VPS;
  float2*   uk2 = (float2*)(VL + 2 * 128 * VPS);  // [2][64] (u, 1/u)
  float*    bks = (float*)(uk2 + 128);            // [2][64] bias - 16

  const int b   = blockIdx.y;
  const int q0  = blockIdx.x * BQ;
  const int tid = threadIdx.x;
  const int w = tid >> 5, lane = tid & 31;
  const int g = lane >> 2, t = lane & 3;
  const int lm = lane >> 3, lr = lane & 7;
  const uint32_t smb = (uint32_t)__cvta_generic_to_shared(usm);
  const uint32_t kcc = ((8 * (lm >> 1) + lr) * KPS + 4 * (lm & 1)) * 4;
  const uint32_t vcc = ((8 * (lm >> 1) + lr) * VPS + 4 * (lm & 1)) * 4;
  const uint32_t VH_OFF = (4 * 64 * KPS) * 4;
  const uint32_t VL_OFF = VH_OFF + (2 * 128 * VPS) * 4;

  // ---- Q fragments direct from global (pre-scaled, packed hi/lo)
  const uint32_t* qhg = QpH + (size_t)(b * NTOK + q0 + w * 16) * 64;
  const uint32_t* qlg = QpL + (size_t)(b * NTOK + q0 + w * 16) * 64;
  uint32_t qah[8][4], qal[8][4];
#pragma unroll
  for (int s = 0; s < 8; s++) {
    qah[s][0] = qhg[g * 64 + 8 * s + t];
    qah[s][1] = qhg[(g + 8) * 64 + 8 * s + t];
    qah[s][2] = qhg[g * 64 + 8 * s + t + 4];
    qah[s][3] = qhg[(g + 8) * 64 + 8 * s + t + 4];
    qal[s][0] = qlg[g * 64 + 8 * s + t];
    qal[s][1] = qlg[(g + 8) * 64 + 8 * s + t];
    qal[s][2] = qlg[g * 64 + 8 * s + t + 4];
    qal[s][3] = qlg[(g + 8) * 64 + 8 * s + t + 4];
  }
  float aq0 = allele[b * NTOK + q0 + w * 16 + g];
  float aq1 = allele[b * NTOK + q0 + w * 16 + g + 8];
  float uq0 = __expf(0.1f * aq0), iq0 = 1.0f / uq0;
  float uq1 = __expf(0.1f * aq1), iq1 = 1.0f / uq1;

  // ---- prefetch tile 0 + packed Wo (one cp group)
  {
    const uint32_t* kh = KpH + (size_t)(b * NTOK) * 64;
    const uint32_t* kl = KpL + (size_t)(b * NTOK) * 64;
#pragma unroll
    for (int it = 0; it < 4; it++) {
      int i = tid + it * 256;
      int r = i >> 4, c = i & 15;
      cp16(&KH[r * KPS + c * 4], kh + r * 64 + c * 4);
      cp16(&KL[r * KPS + c * 4], kl + r * 64 + c * 4);
    }
    const uint32_t* vh = VpH + (size_t)b * DH * (NTOK / 2);
    const uint32_t* vl = VpL + (size_t)b * DH * (NTOK / 2);
#pragma unroll
    for (int it = 0; it < 4; it++) {
      int i = tid + it * 256;
      int r = i >> 3, c = i & 7;
      cp16(&VH[r * VPS + c * 4], vh + (size_t)r * (NTOK / 2) + c * 4);
      cp16(&VL[r * VPS + c * 4], vl + (size_t)r * (NTOK / 2) + c * 4);
    }
    // Wo hi/lo -> smem (rows n, stride XSTR)
#pragma unroll
    for (int it = 0; it < 8; it++) {
      int i = tid + it * 256;
      int r = i >> 4, c = i & 15;
      cp16(usm + WO_U32 + r * XSTR + c * 4, WHg + 3 * 8192 + r * 64 + c * 4);
      cp16(usm + WO_U32 + 8704 + r * XSTR + c * 4,
           WLg + 3 * 8192 + r * 64 + c * 4);
    }
    CP_COMMIT();
    if (tid < BK) {
      float a = allele[b * NTOK + tid];
      float u = __expf(0.1f * a);
      uk2[tid] = make_float2(u, 1.0f / u);
      bks[tid] = (1.0f - mask[b * NTOK + tid]) * -1e9f - 16.0f;
    }
  }

  float o[16][4];
#pragma unroll
  for (int j = 0; j < 16; j++)
#pragma unroll
    for (int q = 0; q < 4; q++) o[j][q] = 0.f;
  float sum0 = 0.f, sum1 = 0.f;   // running exp-sums (fixed shift)

#pragma unroll 1
  for (int kt = 0; kt < NKT; kt++) {
    const int buf = kt & 1;
    CP_WAIT(0);
    __syncthreads();

    if (kt + 1 < NKT) {
      const uint32_t* kh = KpH + (size_t)(b * NTOK + (kt + 1) * BK) * 64;
      const uint32_t* kl = KpL + (size_t)(b * NTOK + (kt + 1) * BK) * 64;
      uint32_t* dkh = KH + (buf ^ 1) * 64 * KPS;
      uint32_t* dkl = KL + (buf ^ 1) * 64 * KPS;
#pragma unroll
      for (int it = 0; it < 4; it++) {
        int i = tid + it * 256;
        int r = i >> 4, c = i & 15;
        cp16(dkh + r * KPS + c * 4, kh + r * 64 + c * 4);
        cp16(dkl + r * KPS + c * 4, kl + r * 64 + c * 4);
      }
      const uint32_t* vh = VpH + (size_t)b * DH * (NTOK / 2) + (kt + 1) * 32;
      const uint32_t* vl = VpL + (size_t)b * DH * (NTOK / 2) + (kt + 1) * 32;
      uint32_t* dvh = VH + (buf ^ 1) * 128 * VPS;
      uint32_t* dvl = VL + (buf ^ 1) * 128 * VPS;
#pragma unroll
      for (int it = 0; it < 4; it++) {
        int i = tid + it * 256;
        int r = i >> 3, c = i & 7;
        cp16(dvh + r * VPS + c * 4, vh + (size_t)r * (NTOK / 2) + c * 4);
        cp16(dvl + r * VPS + c * 4, vl + (size_t)r * (NTOK / 2) + c * 4);
      }
      CP_COMMIT();
      if (tid < BK) {
        float a = allele[b * NTOK + (kt + 1) * BK + tid];
        float u = __expf(0.1f * a);
        uk2[(buf ^ 1) * 64 + tid] = make_float2(u, 1.0f / u);
        bks[(buf ^ 1) * 64 + tid] =
            (1.0f - mask[b * NTOK + (kt + 1) * BK + tid]) * -1e9f - 16.0f;
      }
    }

    // ---- S = Q K^T (m16 x n64 x k128, 3-mma split, ldmatrix B)
    float sacc[8][4];
#pragma unroll
    for (int j = 0; j < 8; j++)
#pragma unroll
      for (int q = 0; q < 4; q++) sacc[j][q] = 0.f;

    const uint32_t khb = smb + (buf * 64 * KPS) * 4;
    const uint32_t klb = smb + ((2 + buf) * 64 * KPS) * 4;
#pragma unroll
    for (int s = 0; s < 8; s++) {
#pragma unroll
      for (int jp = 0; jp < 4; jp++) {
        uint32_t h0, h1, h2, h3, l0_, l1_, l2_, l3_;
        ldsm4(h0, h1, h2, h3, khb + jp * (16 * KPS * 4) + s * 32 + kcc);
        ldsm4(l0_, l1_, l2_, l3_, klb + jp * (16 * KPS * 4) + s * 32 + kcc);
        MMA6_INTERLEAVED(sacc[2 * jp], sacc[2 * jp + 1], qah[s], qal[s],
                         h0, h1, h2, h3, l0_, l1_, l2_, l3_);
      }
    }

    // ---- fixed-shift softmax: P = exp(S*decay + bias') directly
    const float2* ukb = &uk2[buf * 64];
    const float*  bb  = &bks[buf * 64];
    uint32_t pah[4][4], pal[4][4];
#pragma unroll
    for (int j = 0; j < 8; j++) {
      int c = 8 * j + 2 * t;
      float4 uu = *reinterpret_cast<const float4*>(&ukb[c]);
      float2 bias = *reinterpret_cast<const float2*>(&bb[c]);
      float d00 = fminf(uq0 * uu.y, iq0 * uu.x);
      float d01 = fminf(uq0 * uu.w, iq0 * uu.z);
      float d10 = fminf(uq1 * uu.y, iq1 * uu.x);
      float d11 = fminf(uq1 * uu.w, iq1 * uu.z);
      float p00 = __expf(fmaf(sacc[j][0], d00, bias.x));
      float p01 = __expf(fmaf(sacc[j][1], d01, bias.y));
      float p10 = __expf(fmaf(sacc[j][2], d10, bias.x));
      float p11 = __expf(fmaf(sacc[j][3], d11, bias.y));
      sum0 += p00 + p01;
      sum1 += p10 + p11;
      int s2 = j >> 1, sl = (j & 1) * 2;
      pah[s2][sl]     = bfpack(p00, p01);
      pal[s2][sl]     = bfres(pah[s2][sl], p00, p01);
      pah[s2][sl + 1] = bfpack(p10, p11);
      pal[s2][sl + 1] = bfres(pah[s2][sl + 1], p10, p11);
    }

    // ---- O += P V (m16 x n128 x k64)
    const uint32_t vhb = smb + VH_OFF + (buf * 128 * VPS) * 4;
    const uint32_t vlb = smb + VL_OFF + (buf * 128 * VPS) * 4;
#pragma unroll
    for (int s2 = 0; s2 < 4; s2++) {
#pragma unroll
      for (int jp2 = 0; jp2 < 8; jp2++) {
        uint32_t h0, h1, h2, h3, l0_, l1_, l2_, l3_;
        ldsm4(h0, h1, h2, h3, vhb + jp2 * (16 * VPS * 4) + s2 * 32 + vcc);
        ldsm4(l0_, l1_, l2_, l3_, vlb + jp2 * (16 * VPS * 4) + s2 * 32 + vcc);
        MMA6_INTERLEAVED(o[2 * jp2], o[2 * jp2 + 1], pah[s2], pal[s2],
                         h0, h1, h2, h3, l0_, l1_, l2_, l3_);
      }
    }
  }

  // ---- epilogue: normalize, then out = ctx @ Wo fused in-register.
  sum0 += __shfl_xor_sync(0xffffffffu, sum0, 1);
  sum0 += __shfl_xor_sync(0xffffffffu, sum0, 2);
  sum1 += __shfl_xor_sync(0xffffffffu, sum1, 1);
  sum1 += __shfl_xor_sync(0xffffffffu, sum1, 2);
  float inv0 = 1.0f / sum0, inv1 = 1.0f / sum1;

  const uint32_t wohb = smb + WO_U32 * 4;
  const uint32_t wolb = wohb + 8704 * 4;
  const uint32_t wcc = ((8 * (lm >> 1) + lr) * XSTR + 4 * (lm & 1)) * 4;

  float out[16][4];
#pragma unroll
  for (int j = 0; j < 16; j++)
#pragma unroll
    for (int q = 0; q < 4; q++) out[j][q] = 0.f;

#pragma unroll
  for (int s = 0; s < 8; s++) {
    float f0 = o[2 * s][0] * inv0, f1 = o[2 * s][1] * inv0;
    float f2 = o[2 * s][2] * inv1, f3 = o[2 * s][3] * inv1;
    float e0 = o[2 * s + 1][0] * inv0, e1 = o[2 * s + 1][1] * inv0;
    float e2 = o[2 * s + 1][2] * inv1, e3 = o[2 * s + 1][3] * inv1;
    uint32_t cah[4], cal[4];
    cah[0] = bfpack(f0, f1); cal[0] = bfres(cah[0], f0, f1);
    cah[1] = bfpack(f2, f3); cal[1] = bfres(cah[1], f2, f3);
    cah[2] = bfpack(e0, e1); cal[2] = bfres(cah[2], e0, e1);
    cah[3] = bfpack(e2, e3); cal[3] = bfres(cah[3], e2, e3);
#pragma unroll
    for (int jp = 0; jp < 8; jp++) {
      uint32_t h0, h1, h2, h3, l0_, l1_, l2_, l3_;
      ldsm4(h0, h1, h2, h3, wohb + jp * (16 * XSTR * 4) + s * 32 + wcc);
      ldsm4(l0_, l1_, l2_, l3_, wolb + jp * (16 * XSTR * 4) + s * 32 + wcc);
      MMA6_INTERLEAVED(out[2 * jp], out[2 * jp + 1], cah, cal,
                       h0, h1, h2, h3, l0_, l1_, l2_, l3_);
    }
  }

  float* Og = Out + (size_t)(b * NTOK + q0) * DH;
#pragma unroll
  for (int j2 = 0; j2 < 16; j2++) {
    *reinterpret_cast<float2*>(&Og[(w * 16 + g) * DH + 8 * j2 + 2 * t]) =
        make_float2(out[j2][0], out[j2][1]);
    *reinterpret_cast<float2*>(&Og[(w * 16 + g + 8) * DH + 8 * j2 + 2 * t]) =
        make_float2(out[j2][2], out[j2][3]);
  }
}

// ---------------------------------------------------------------------------
extern "C" void kernel_launch(void* const* d_in, const int* in_sizes, int n_in,
                              void* d_out, int out_size) {
  const float* X  = (const float*)d_in[0];
  const float* al = (const float*)d_in[1];
  const float* mk = (const float*)d_in[2];
  const float* Wq = (const float*)d_in[3];
  const float* Wk = (const float*)d_in[4];
  const float* Wv = (const float*)d_in[5];
  const float* Wo = (const float*)d_in[6];
  float* out = (float*)d_out;

  uint32_t *qh, *ql, *kh, *kl, *vh, *vl, *wh, *wl;
  cudaGetSymbolAddress((void**)&qh, g_qh);
  cudaGetSymbolAddress((void**)&ql, g_ql);
  cudaGetSymbolAddress((void**)&kh, g_kh);
  cudaGetSymbolAddress((void**)&kl, g_kl);
  cudaGetSymbolAddress((void**)&vh, g_vh);
  cudaGetSymbolAddress((void**)&vl, g_vl);
  cudaGetSymbolAddress((void**)&wh, g_wh);
  cudaGetSymbolAddress((void**)&wl, g_wl);

  cudaFuncSetAttribute(qkv_kernel,
                       cudaFuncAttributeMaxDynamicSharedMemorySize, QKV_SMEM);
  cudaFuncSetAttribute(attn_kernel,
                       cudaFuncAttributeMaxDynamicSharedMemorySize, ATTN_SMEM);

  wpack_kernel<<<dim3(4, 4), 256>>>(Wq, Wk, Wv, Wo, wh, wl);
  qkv_kernel<<<NB * NTOK / 128, 256, QKV_SMEM>>>(X, wh, wl, qh, ql, kh, kl, vh, vl);
  attn_kernel<<<dim3(NTOK / BQ, NB), 256, ATTN_SMEM>>>(qh, ql, kh, kl, vh, vl,
                                                       wh, wl, al, mk, out);
}

// round 16
// speedup vs baseline: 1.0231x; 1.0128x over previous
#include <cuda_runtime.h>
#include <cuda_bf16.h>
#include <stdint.h>

#define NB   8
#define NTOK 2048
#define DH   128
#define BQ   128          // attention q-rows per block (8 warps x m16)
#define BK   64
#define NKT  (NTOK / BK)   // 32
#define KPS  68            // K smem row stride (uint32)
#define VPS  36            // V^T smem row stride (uint32)
#define XSTR 68            // proj smem stride (uint32)

// ---- packed bf16 hi/lo scratch (pairs in uint32) ----
__device__ uint32_t g_qh[NB * NTOK * 64];
__device__ uint32_t g_ql[NB * NTOK * 64];
__device__ uint32_t g_kh[NB * NTOK * 64];
__device__ uint32_t g_kl[NB * NTOK * 64];
__device__ uint32_t g_vh[NB * DH * (NTOK / 2)];   // V transposed: [b][d][tokenpair]
__device__ uint32_t g_vl[NB * DH * (NTOK / 2)];
__device__ uint32_t g_wh[4 * 128 * 64];           // packed W: [proj][n][kpair]
__device__ uint32_t g_wl[4 * 128 * 64];

// attention smem (u32 offsets): K(2buf) | KL | V(2buf) | VL | uk2 | bks | WoH | WoL
#define KV_U32   (4 * 64 * KPS + 4 * 128 * VPS)   // 35840
#define WO_U32   (KV_U32 + 256 + 128)             // 36224
#define ATTN_U32 (WO_U32 + 2 * 8704)              // 53632
#define ATTN_SMEM (ATTN_U32 * 4)                  // 214528 B (1 block/SM)

#define QKV_SMEM  ((2 * 128 * XSTR + 2 * 2 * 128 * XSTR) * 4)  // X + 2 W bufs

// m16n8k16 bf16 mma, D += A*B
#define MMA_BF16(d, a, b0, b1)                                                 \
  asm volatile(                                                                \
      "mma.sync.aligned.m16n8k16.row.col.f32.bf16.bf16.f32 "                   \
      "{%0,%1,%2,%3}, {%4,%5,%6,%7}, {%8,%9}, {%0,%1,%2,%3};"                  \
      : "+f"(d[0]), "+f"(d[1]), "+f"(d[2]), "+f"(d[3])                         \
      : "r"(a[0]), "r"(a[1]), "r"(a[2]), "r"(a[3]), "r"(b0), "r"(b1))

#define MMA6_INTERLEAVED(dA, dB, ah, al, h0, h1, h2, h3, l0, l1, l2, l3)       \
  do {                                                                         \
    MMA_BF16(dA, ah, h0, h1);                                                  \
    MMA_BF16(dB, ah, h2, h3);                                                  \
    MMA_BF16(dA, al, h0, h1);                                                  \
    MMA_BF16(dB, al, h2, h3);                                                  \
    MMA_BF16(dA, ah, l0, l1);                                                  \
    MMA_BF16(dB, ah, l2, l3);                                                  \
  } while (0)

__device__ __forceinline__ void ldsm4(uint32_t& r0, uint32_t& r1, uint32_t& r2,
                                      uint32_t& r3, uint32_t saddr) {
  asm volatile(
      "ldmatrix.sync.aligned.m8n8.x4.shared.b16 {%0,%1,%2,%3}, [%4];"
      : "=r"(r0), "=r"(r1), "=r"(r2), "=r"(r3)
      : "r"(saddr));
}

__device__ __forceinline__ uint32_t bfpack(float e, float o) {
  uint32_t r;
  asm("cvt.rn.bf16x2.f32 %0, %1, %2;" : "=r"(r) : "f"(o), "f"(e));
  return r;
}
__device__ __forceinline__ float bflo(uint32_t p) { return __uint_as_float(p << 16); }
__device__ __forceinline__ float bfhi(uint32_t p) { return __uint_as_float(p & 0xffff0000u); }
__device__ __forceinline__ uint32_t bfres(uint32_t h, float e, float o) {
  return bfpack(e - bflo(h), o - bfhi(h));
}

__device__ __forceinline__ void cp16(void* smem_dst, const void* gmem_src) {
  unsigned s = (unsigned)__cvta_generic_to_shared(smem_dst);
  asm volatile("cp.async.cg.shared.global [%0], [%1], 16;" ::"r"(s), "l"(gmem_src));
}
#define CP_COMMIT() asm volatile("cp.async.commit_group;")
#define CP_WAIT(n)  asm volatile("cp.async.wait_group %0;" ::"n"(n))

// ---------------------------------------------------------------------------
// Weight pre-pack: W[128k][128n] fp32 -> packed hi/lo [n][kpair] u32.
// Wq is pre-scaled by 1/sqrt(128) (folded out of the qkv Q epilogue).
// ---------------------------------------------------------------------------
__global__ __launch_bounds__(256) void wpack_kernel(
    const float* __restrict__ Wq, const float* __restrict__ Wk,
    const float* __restrict__ Wv, const float* __restrict__ Wo,
    uint32_t* __restrict__ WH, uint32_t* __restrict__ WL) {
  __shared__ float Ws[32 * 132];
  const int ks = blockIdx.x, pj = blockIdx.y;
  const float* W = (pj == 0) ? Wq : (pj == 1) ? Wk : (pj == 2) ? Wv : Wo;
  const float sc = (pj == 0) ? 0.088388347648318447f : 1.0f;
  const int tid = threadIdx.x;
#pragma unroll
  for (int it = 0; it < 16; it++) {
    int i = tid + it * 256;
    int kr = i >> 7, n = i & 127;
    Ws[kr * 132 + n] = W[(ks * 32 + kr) * 128 + n] * sc;
  }
  __syncthreads();
#pragma unroll
  for (int it = 0; it < 8; it++) {
    int i = tid + it * 256;
    int n = i >> 4, kp = i & 15;
    float w0 = Ws[(2 * kp) * 132 + n];
    float w1 = Ws[(2 * kp + 1) * 132 + n];
    uint32_t h = bfpack(w0, w1);
    WH[pj * 8192 + n * 64 + ks * 16 + kp] = h;
    WL[pj * 8192 + n * 64 + ks * 16 + kp] = bfres(h, w0, w1);
  }
}

// ---------------------------------------------------------------------------
// Fused QKV projections: 128-token tiles, X staged in smem, packed W via
// double-buffered cp.async, 3 phases. Q/K epilogues bounce through the dead
// X smem region for fully-coalesced STG.128 output.
// ---------------------------------------------------------------------------
__global__ __launch_bounds__(256, 1) void qkv_kernel(
    const float* __restrict__ X, const uint32_t* __restrict__ WHg,
    const uint32_t* __restrict__ WLg,
    uint32_t* __restrict__ Qh, uint32_t* __restrict__ Ql,
    uint32_t* __restrict__ Kh, uint32_t* __restrict__ Kl,
    uint32_t* __restrict__ Vh, uint32_t* __restrict__ Vl) {
  extern __shared__ uint32_t usm[];
  uint32_t* Xh = usm;                  // [128][XSTR]; dead after frag load
  uint32_t* Xl = Xh + 128 * XSTR;      // (reused as Q/K bounce buffers)

  const int m0  = blockIdx.x * 128;
  const int tid = threadIdx.x;
  const int w = tid >> 5, lane = tid & 31;
  const int g = lane >> 2, t = lane & 3;
  const int r0 = w * 16 + g, r1 = r0 + 8;
  const int lm = lane >> 3, lr = lane & 7;
  const uint32_t smb = (uint32_t)__cvta_generic_to_shared(usm);
  const uint32_t wcc = ((8 * (lm >> 1) + lr) * XSTR + 4 * (lm & 1)) * 4;

  // prologue: prefetch W0
#pragma unroll
  for (int it = 0; it < 8; it++) {
    int i = tid + it * 256;
    int r = i >> 4, c = i & 15;
    cp16(usm + 17408 + r * XSTR + c * 4, WHg + r * 64 + c * 4);
    cp16(usm + 17408 + 8704 + r * XSTR + c * 4, WLg + r * 64 + c * 4);
  }
  CP_COMMIT();

  // stage X split+packed (overlaps W0 load)
#pragma unroll
  for (int it = 0; it < 16; it++) {
    int i = tid + it * 256;
    int r = i >> 5, c4 = i & 31;
    float4 xv = reinterpret_cast<const float4*>(X)[(size_t)(m0 + r) * 32 + c4];
    uint32_t h0 = bfpack(xv.x, xv.y), h1 = bfpack(xv.z, xv.w);
    Xh[r * XSTR + 2 * c4]     = h0;
    Xh[r * XSTR + 2 * c4 + 1] = h1;
    Xl[r * XSTR + 2 * c4]     = bfres(h0, xv.x, xv.y);
    Xl[r * XSTR + 2 * c4 + 1] = bfres(h1, xv.z, xv.w);
  }
  __syncthreads();

  uint32_t xah[8][4], xal[8][4];
#pragma unroll
  for (int s = 0; s < 8; s++) {
    xah[s][0] = Xh[r0 * XSTR + 8 * s + t];
    xah[s][1] = Xh[r1 * XSTR + 8 * s + t];
    xah[s][2] = Xh[r0 * XSTR + 8 * s + t + 4];
    xah[s][3] = Xh[r1 * XSTR + 8 * s + t + 4];
    xal[s][0] = Xl[r0 * XSTR + 8 * s + t];
    xal[s][1] = Xl[r1 * XSTR + 8 * s + t];
    xal[s][2] = Xl[r0 * XSTR + 8 * s + t + 4];
    xal[s][3] = Xl[r1 * XSTR + 8 * s + t + 4];
  }

#pragma unroll 1
  for (int ph = 0; ph < 3; ph++) {
    if (ph < 2) {
      const uint32_t buf1 = ((ph + 1) & 1);
      uint32_t* wb = usm + 17408 + buf1 * 17408;
#pragma unroll
      for (int it = 0; it < 8; it++) {
        int i = tid + it * 256;
        int r = i >> 4, c = i & 15;
        cp16(wb + r * XSTR + c * 4, WHg + (ph + 1) * 8192 + r * 64 + c * 4);
        cp16(wb + 8704 + r * XSTR + c * 4, WLg + (ph + 1) * 8192 + r * 64 + c * 4);
      }
      CP_COMMIT();
      CP_WAIT(1);
    } else {
      CP_WAIT(0);
    }
    __syncthreads();

    const uint32_t whb = smb + (17408 + (ph & 1) * 17408) * 4;
    const uint32_t wlb = whb + 8704 * 4;

    float acc[16][4];
#pragma unroll
    for (int j = 0; j < 16; j++)
#pragma unroll
      for (int q = 0; q < 4; q++) acc[j][q] = 0.f;

#pragma unroll
    for (int s = 0; s < 8; s++) {
#pragma unroll
      for (int jp = 0; jp < 8; jp++) {
        uint32_t h0, h1, h2, h3, l0, l1, l2, l3;
        ldsm4(h0, h1, h2, h3, whb + jp * (16 * XSTR * 4) + s * 32 + wcc);
        ldsm4(l0, l1, l2, l3, wlb + jp * (16 * XSTR * 4) + s * 32 + wcc);
        MMA6_INTERLEAVED(acc[2 * jp], acc[2 * jp + 1], xah[s], xal[s],
                         h0, h1, h2, h3, l0, l1, l2, l3);
      }
    }

    if (ph < 2) {
      // Q/K epilogue: bounce through X region (dead), coalesced copy out.
      // STS banks: (4g + 4j + t) mod 32 -> conflict-free (stride 68).
#pragma unroll
      for (int j = 0; j < 16; j++) {
        float a0 = acc[j][0], a1 = acc[j][1];
        float a2 = acc[j][2], a3 = acc[j][3];
        uint32_t h0 = bfpack(a0, a1), h1 = bfpack(a2, a3);
        Xh[r0 * XSTR + 4 * j + t] = h0;
        Xl[r0 * XSTR + 4 * j + t] = bfres(h0, a0, a1);
        Xh[r1 * XSTR + 4 * j + t] = h1;
        Xl[r1 * XSTR + 4 * j + t] = bfres(h1, a2, a3);
      }
      __syncthreads();
      uint32_t* Oh = (ph == 0) ? Qh : Kh;
      uint32_t* Ol = (ph == 0) ? Ql : Kl;
      // full tile: 128 tokens x 64 u32 = 2048 uint4 chunks
#pragma unroll
      for (int it = 0; it < 8; it++) {
        int i = tid + it * 256;   // 0..2047
        int r = i >> 4, c = i & 15;
        *reinterpret_cast<uint4*>(&Oh[(size_t)(m0 + r) * 64 + c * 4]) =
            *reinterpret_cast<const uint4*>(&Xh[r * XSTR + c * 4]);
        *reinterpret_cast<uint4*>(&Ol[(size_t)(m0 + r) * 64 + c * 4]) =
            *reinterpret_cast<const uint4*>(&Xl[r * XSTR + c * 4]);
      }
      // no trailing sync needed: next iteration's top sync guards reuse
    } else {
      // V: transpose via the free W buffer, pack pairs over tokens
      __syncthreads();
      uint16_t* Th = (uint16_t*)(usm + 17408 + 17408);  // [128 d][132 tok]
      uint16_t* Tl = Th + 128 * 132;
#pragma unroll
      for (int j = 0; j < 16; j++) {
        int c0 = 8 * j + 2 * t, c1 = c0 + 1;
#pragma unroll
        for (int q = 0; q < 4; q++) {
          int c = (q & 1) ? c1 : c0;
          int r = (q & 2) ? r1 : r0;
          float x = acc[j][q];
          __nv_bfloat16 h = __float2bfloat16(x);
          Th[c * 132 + r] = __bfloat16_as_ushort(h);
          Tl[c * 132 + r] =
              __bfloat16_as_ushort(__float2bfloat16(x - __bfloat162float(h)));
        }
      }
      __syncthreads();
      const int bb = m0 >> 11;
      const int loc2 = (m0 & 2047) >> 1;
      const uint32_t* Th32 = (const uint32_t*)Th;
      const uint32_t* Tl32 = (const uint32_t*)Tl;
#pragma unroll
      for (int it = 0; it < 32; it++) {
        int i = tid + it * 256;
        int d = i >> 6, m = i & 63;
        size_t go = (size_t)(bb * DH + d) * (NTOK / 2) + loc2 + m;
        Vh[go] = Th32[d * 66 + m];
        Vl[go] = Tl32[d * 66 + m];
      }
    }
  }
}

// ---------------------------------------------------------------------------
// Fused flash attention + output projection (unchanged 184.9us winner).
// ---------------------------------------------------------------------------
__global__ __launch_bounds__(256, 1) void attn_kernel(
    const uint32_t* __restrict__ QpH, const uint32_t* __restrict__ QpL,
    const uint32_t* __restrict__ KpH, const uint32_t* __restrict__ KpL,
    const uint32_t* __restrict__ VpH, const uint32_t* __restrict__ VpL,
    const uint32_t* __restrict__ WHg, const uint32_t* __restrict__ WLg,
    const float* __restrict__ allele, const float* __restrict__ mask,
    float* __restrict__ Out) {
  extern __shared__ uint32_t usm[];
  uint32_t* KH = usm;                      // [2][64*KPS]
  uint32_t* KL = KH + 2 * 64 * KPS;
  uint32_t* VH = KL + 2 * 64 * KPS;        // [2][128*VPS]
  uint32_t* VL = VH + 2 * 128 * VPS;
  float2*   uk2 = (float2*)(VL + 2 * 128 * VPS);  // [2][64] (u, 1/u)
  float*    bks = (float*)(uk2 + 128);            // [2][64] bias - 16

  const int b   = blockIdx.y;
  const int q0  = blockIdx.x * BQ;
  const int tid = threadIdx.x;
  const int w = tid >> 5, lane = tid & 31;
  const int g = lane >> 2, t = lane & 3;
  const int lm = lane >> 3, lr = lane & 7;
  const uint32_t smb = (uint32_t)__cvta_generic_to_shared(usm);
  const uint32_t kcc = ((8 * (lm >> 1) + lr) * KPS + 4 * (lm & 1)) * 4;
  const uint32_t vcc = ((8 * (lm >> 1) + lr) * VPS + 4 * (lm & 1)) * 4;
  const uint32_t VH_OFF = (4 * 64 * KPS) * 4;
  const uint32_t VL_OFF = VH_OFF + (2 * 128 * VPS) * 4;

  // ---- Q fragments direct from global (pre-scaled, packed hi/lo)
  const uint32_t* qhg = QpH + (size_t)(b * NTOK + q0 + w * 16) * 64;
  const uint32_t* qlg = QpL + (size_t)(b * NTOK + q0 + w * 16) * 64;
  uint32_t qah[8][4], qal[8][4];
#pragma unroll
  for (int s = 0; s < 8; s++) {
    qah[s][0] = qhg[g * 64 + 8 * s + t];
    qah[s][1] = qhg[(g + 8) * 64 + 8 * s + t];
    qah[s][2] = qhg[g * 64 + 8 * s + t + 4];
    qah[s][3] = qhg[(g + 8) * 64 + 8 * s + t + 4];
    qal[s][0] = qlg[g * 64 + 8 * s + t];
    qal[s][1] = qlg[(g + 8) * 64 + 8 * s + t];
    qal[s][2] = qlg[g * 64 + 8 * s + t + 4];
    qal[s][3] = qlg[(g + 8) * 64 + 8 * s + t + 4];
  }
  float aq0 = allele[b * NTOK + q0 + w * 16 + g];
  float aq1 = allele[b * NTOK + q0 + w * 16 + g + 8];
  float uq0 = __expf(0.1f * aq0), iq0 = 1.0f / uq0;
  float uq1 = __expf(0.1f * aq1), iq1 = 1.0f / uq1;

  // ---- prefetch tile 0 + packed Wo (one cp group)
  {
    const uint32_t* kh = KpH + (size_t)(b * NTOK) * 64;
    const uint32_t* kl = KpL + (size_t)(b * NTOK) * 64;
#pragma unroll
    for (int it = 0; it < 4; it++) {
      int i = tid + it * 256;
      int r = i >> 4, c = i & 15;
      cp16(&KH[r * KPS + c * 4], kh + r * 64 + c * 4);
      cp16(&KL[r * KPS + c * 4], kl + r * 64 + c * 4);
    }
    const uint32_t* vh = VpH + (size_t)b * DH * (NTOK / 2);
    const uint32_t* vl = VpL + (size_t)b * DH * (NTOK / 2);
#pragma unroll
    for (int it = 0; it < 4; it++) {
      int i = tid + it * 256;
      int r = i >> 3, c = i & 7;
      cp16(&VH[r * VPS + c * 4], vh + (size_t)r * (NTOK / 2) + c * 4);
      cp16(&VL[r * VPS + c * 4], vl + (size_t)r * (NTOK / 2) + c * 4);
    }
    // Wo hi/lo -> smem (rows n, stride XSTR)
#pragma unroll
    for (int it = 0; it < 8; it++) {
      int i = tid + it * 256;
      int r = i >> 4, c = i & 15;
      cp16(usm + WO_U32 + r * XSTR + c * 4, WHg + 3 * 8192 + r * 64 + c * 4);
      cp16(usm + WO_U32 + 8704 + r * XSTR + c * 4,
           WLg + 3 * 8192 + r * 64 + c * 4);
    }
    CP_COMMIT();
    if (tid < BK) {
      float a = allele[b * NTOK + tid];
      float u = __expf(0.1f * a);
      uk2[tid] = make_float2(u, 1.0f / u);
      bks[tid] = (1.0f - mask[b * NTOK + tid]) * -1e9f - 16.0f;
    }
  }

  float o[16][4];
#pragma unroll
  for (int j = 0; j < 16; j++)
#pragma unroll
    for (int q = 0; q < 4; q++) o[j][q] = 0.f;
  float sum0 = 0.f, sum1 = 0.f;   // running exp-sums (fixed shift)

#pragma unroll 1
  for (int kt = 0; kt < NKT; kt++) {
    const int buf = kt & 1;
    CP_WAIT(0);
    __syncthreads();

    if (kt + 1 < NKT) {
      const uint32_t* kh = KpH + (size_t)(b * NTOK + (kt + 1) * BK) * 64;
      const uint32_t* kl = KpL + (size_t)(b * NTOK + (kt + 1) * BK) * 64;
      uint32_t* dkh = KH + (buf ^ 1) * 64 * KPS;
      uint32_t* dkl = KL + (buf ^ 1) * 64 * KPS;
#pragma unroll
      for (int it = 0; it < 4; it++) {
        int i = tid + it * 256;
        int r = i >> 4, c = i & 15;
        cp16(dkh + r * KPS + c * 4, kh + r * 64 + c * 4);
        cp16(dkl + r * KPS + c * 4, kl + r * 64 + c * 4);
      }
      const uint32_t* vh = VpH + (size_t)b * DH * (NTOK / 2) + (kt + 1) * 32;
      const uint32_t* vl = VpL + (size_t)b * DH * (NTOK / 2) + (kt + 1) * 32;
      uint32_t* dvh = VH + (buf ^ 1) * 128 * VPS;
      uint32_t* dvl = VL + (buf ^ 1) * 128 * VPS;
#pragma unroll
      for (int it = 0; it < 4; it++) {
        int i = tid + it * 256;
        int r = i >> 3, c = i & 7;
        cp16(dvh + r * VPS + c * 4, vh + (size_t)r * (NTOK / 2) + c * 4);
        cp16(dvl + r * VPS + c * 4, vl + (size_t)r * (NTOK / 2) + c * 4);
      }
      CP_COMMIT();
      if (tid < BK) {
        float a = allele[b * NTOK + (kt + 1) * BK + tid];
        float u = __expf(0.1f * a);
        uk2[(buf ^ 1) * 64 + tid] = make_float2(u, 1.0f / u);
        bks[(buf ^ 1) * 64 + tid] =
            (1.0f - mask[b * NTOK + (kt + 1) * BK + tid]) * -1e9f - 16.0f;
      }
    }

    // ---- S = Q K^T (m16 x n64 x k128, 3-mma split, ldmatrix B)
    float sacc[8][4];
#pragma unroll
    for (int j = 0; j < 8; j++)
#pragma unroll
      for (int q = 0; q < 4; q++) sacc[j][q] = 0.f;

    const uint32_t khb = smb + (buf * 64 * KPS) * 4;
    const uint32_t klb = smb + ((2 + buf) * 64 * KPS) * 4;
#pragma unroll
    for (int s = 0; s < 8; s++) {
#pragma unroll
      for (int jp = 0; jp < 4; jp++) {
        uint32_t h0, h1, h2, h3, l0_, l1_, l2_, l3_;
        ldsm4(h0, h1, h2, h3, khb + jp * (16 * KPS * 4) + s * 32 + kcc);
        ldsm4(l0_, l1_, l2_, l3_, klb + jp * (16 * KPS * 4) + s * 32 + kcc);
        MMA6_INTERLEAVED(sacc[2 * jp], sacc[2 * jp + 1], qah[s], qal[s],
                         h0, h1, h2, h3, l0_, l1_, l2_, l3_);
      }
    }

    // ---- fixed-shift softmax: P = exp(S*decay + bias') directly
    const float2* ukb = &uk2[buf * 64];
    const float*  bb  = &bks[buf * 64];
    uint32_t pah[4][4], pal[4][4];
#pragma unroll
    for (int j = 0; j < 8; j++) {
      int c = 8 * j + 2 * t;
      float4 uu = *reinterpret_cast<const float4*>(&ukb[c]);
      float2 bias = *reinterpret_cast<const float2*>(&bb[c]);
      float d00 = fminf(uq0 * uu.y, iq0 * uu.x);
      float d01 = fminf(uq0 * uu.w, iq0 * uu.z);
      float d10 = fminf(uq1 * uu.y, iq1 * uu.x);
      float d11 = fminf(uq1 * uu.w, iq1 * uu.z);
      float p00 = __expf(fmaf(sacc[j][0], d00, bias.x));
      float p01 = __expf(fmaf(sacc[j][1], d01, bias.y));
      float p10 = __expf(fmaf(sacc[j][2], d10, bias.x));
      float p11 = __expf(fmaf(sacc[j][3], d11, bias.y));
      sum0 += p00 + p01;
      sum1 += p10 + p11;
      int s2 = j >> 1, sl = (j & 1) * 2;
      pah[s2][sl]     = bfpack(p00, p01);
      pal[s2][sl]     = bfres(pah[s2][sl], p00, p01);
      pah[s2][sl + 1] = bfpack(p10, p11);
      pal[s2][sl + 1] = bfres(pah[s2][sl + 1], p10, p11);
    }

    // ---- O += P V (m16 x n128 x k64)
    const uint32_t vhb = smb + VH_OFF + (buf * 128 * VPS) * 4;
    const uint32_t vlb = smb + VL_OFF + (buf * 128 * VPS) * 4;
#pragma unroll
    for (int s2 = 0; s2 < 4; s2++) {
#pragma unroll
      for (int jp2 = 0; jp2 < 8; jp2++) {
        uint32_t h0, h1, h2, h3, l0_, l1_, l2_, l3_;
        ldsm4(h0, h1, h2, h3, vhb + jp2 * (16 * VPS * 4) + s2 * 32 + vcc);
        ldsm4(l0_, l1_, l2_, l3_, vlb + jp2 * (16 * VPS * 4) + s2 * 32 + vcc);
        MMA6_INTERLEAVED(o[2 * jp2], o[2 * jp2 + 1], pah[s2], pal[s2],
                         h0, h1, h2, h3, l0_, l1_, l2_, l3_);
      }
    }
  }

  // ---- epilogue: normalize, then out = ctx @ Wo fused in-register.
  sum0 += __shfl_xor_sync(0xffffffffu, sum0, 1);
  sum0 += __shfl_xor_sync(0xffffffffu, sum0, 2);
  sum1 += __shfl_xor_sync(0xffffffffu, sum1, 1);
  sum1 += __shfl_xor_sync(0xffffffffu, sum1, 2);
  float inv0 = 1.0f / sum0, inv1 = 1.0f / sum1;

  const uint32_t wohb = smb + WO_U32 * 4;
  const uint32_t wolb = wohb + 8704 * 4;
  const uint32_t wcc = ((8 * (lm >> 1) + lr) * XSTR + 4 * (lm & 1)) * 4;

  float out[16][4];
#pragma unroll
  for (int j = 0; j < 16; j++)
#pragma unroll
    for (int q = 0; q < 4; q++) out[j][q] = 0.f;

#pragma unroll
  for (int s = 0; s < 8; s++) {
    float f0 = o[2 * s][0] * inv0, f1 = o[2 * s][1] * inv0;
    float f2 = o[2 * s][2] * inv1, f3 = o[2 * s][3] * inv1;
    float e0 = o[2 * s + 1][0] * inv0, e1 = o[2 * s + 1][1] * inv0;
    float e2 = o[2 * s + 1][2] * inv1, e3 = o[2 * s + 1][3] * inv1;
    uint32_t cah[4], cal[4];
    cah[0] = bfpack(f0, f1); cal[0] = bfres(cah[0], f0, f1);
    cah[1] = bfpack(f2, f3); cal[1] = bfres(cah[1], f2, f3);
    cah[2] = bfpack(e0, e1); cal[2] = bfres(cah[2], e0, e1);
    cah[3] = bfpack(e2, e3); cal[3] = bfres(cah[3], e2, e3);
#pragma unroll
    for (int jp = 0; jp < 8; jp++) {
      uint32_t h0, h1, h2, h3, l0_, l1_, l2_, l3_;
      ldsm4(h0, h1, h2, h3, wohb + jp * (16 * XSTR * 4) + s * 32 + wcc);
      ldsm4(l0_, l1_, l2_, l3_, wolb + jp * (16 * XSTR * 4) + s * 32 + wcc);
      MMA6_INTERLEAVED(out[2 * jp], out[2 * jp + 1], cah, cal,
                       h0, h1, h2, h3, l0_, l1_, l2_, l3_);
    }
  }

  float* Og = Out + (size_t)(b * NTOK + q0) * DH;
#pragma unroll
  for (int j2 = 0; j2 < 16; j2++) {
    *reinterpret_cast<float2*>(&Og[(w * 16 + g) * DH + 8 * j2 + 2 * t]) =
        make_float2(out[j2][0], out[j2][1]);
    *reinterpret_cast<float2*>(&Og[(w * 16 + g + 8) * DH + 8 * j2 + 2 * t]) =
        make_float2(out[j2][2], out[j2][3]);
  }
}

// ---------------------------------------------------------------------------
extern "C" void kernel_launch(void* const* d_in, const int* in_sizes, int n_in,
                              void* d_out, int out_size) {
  const float* X  = (const float*)d_in[0];
  const float* al = (const float*)d_in[1];
  const float* mk = (const float*)d_in[2];
  const float* Wq = (const float*)d_in[3];
  const float* Wk = (const float*)d_in[4];
  const float* Wv = (const float*)d_in[5];
  const float* Wo = (const float*)d_in[6];
  float* out = (float*)d_out;

  uint32_t *qh, *ql, *kh, *kl, *vh, *vl, *wh, *wl;
  cudaGetSymbolAddress((void**)&qh, g_qh);
  cudaGetSymbolAddress((void**)&ql, g_ql);
  cudaGetSymbolAddress((void**)&kh, g_kh);
  cudaGetSymbolAddress((void**)&kl, g_kl);
  cudaGetSymbolAddress((void**)&vh, g_vh);
  cudaGetSymbolAddress((void**)&vl, g_vl);
  cudaGetSymbolAddress((void**)&wh, g_wh);
  cudaGetSymbolAddress((void**)&wl, g_wl);

  cudaFuncSetAttribute(qkv_kernel,
                       cudaFuncAttributeMaxDynamicSharedMemorySize, QKV_SMEM);
  cudaFuncSetAttribute(attn_kernel,
                       cudaFuncAttributeMaxDynamicSharedMemorySize, ATTN_SMEM);

  wpack_kernel<<<dim3(4, 4), 256>>>(Wq, Wk, Wv, Wo, wh, wl);
  qkv_kernel<<<NB * NTOK / 128, 256, QKV_SMEM>>>(X, wh, wl, qh, ql, kh, kl, vh, vl);
  attn_kernel<<<dim3(NTOK / BQ, NB), 256, ATTN_SMEM>>>(qh, ql, kh, kl, vh, vl,
                                                       wh, wl, al, mk, out);
}